// round 1
// baseline (speedup 1.0000x reference)
#include <cuda_runtime.h>
#include <cuda_bf16.h>
#include <cstdint>

// Problem constants
#define NRES 768
#define SMSA 512
#define TF   21
#define MSADIM 49
#define CZ   128
#define CM   256
#define MSA_OUT_ELEMS (512u*768u*256u)   // 100663296
#define ROWS_TOTAL (512*768)             // 393216

typedef unsigned long long ull;

// ---------------- device scratch (no allocations allowed) ----------------
__device__ float g_tfi[NRES * CZ];     // target@w_tf_z_i + b
__device__ float g_tfj[NRES * CZ];     // target@w_tf_z_j + b
__device__ float g_comb[NRES * CM];    // target@w_tf_m + b_tf_m + b_msa_m

// ---------------- f32x2 helpers ----------------
__device__ __forceinline__ ull fma2(ull a, ull b, ull c) {
    ull d;
    asm("fma.rn.f32x2 %0, %1, %2, %3;" : "=l"(d) : "l"(a), "l"(b), "l"(c));
    return d;
}
__device__ __forceinline__ ull pack2(float x, float y) {
    ull d;
    asm("mov.b64 %0, {%1, %2};" : "=l"(d) : "f"(x), "f"(y));
    return d;
}
__device__ __forceinline__ float2 unpack2(ull a) {
    float2 v;
    asm("mov.b64 {%0, %1}, %2;" : "=f"(v.x), "=f"(v.y) : "l"(a));
    return v;
}

// ---------------- kernel 1: tiny precompute ----------------
// grid=768 blocks, 256 threads. Computes per-residue embeddings.
__global__ void pre_kernel(const float* __restrict__ tf,
                           const float* __restrict__ wzi, const float* __restrict__ bzi,
                           const float* __restrict__ wzj, const float* __restrict__ bzj,
                           const float* __restrict__ wm,  const float* __restrict__ bm,
                           const float* __restrict__ bmsa) {
    __shared__ float t[TF];
    int i = blockIdx.x;
    int c = threadIdx.x;
    if (c < TF) t[c] = tf[i * TF + c];
    __syncthreads();

    // comb (256 channels)
    float am = bm[c] + bmsa[c];
#pragma unroll
    for (int k = 0; k < TF; k++) am += t[k] * wm[k * CM + c];
    g_comb[i * CM + c] = am;

    if (c < CZ) {
        float ai = bzi[c];
        float aj = bzj[c];
#pragma unroll
        for (int k = 0; k < TF; k++) {
            float tv = t[k];
            ai += tv * wzi[k * CZ + c];
            aj += tv * wzj[k * CZ + c];
        }
        g_tfi[i * CZ + c] = ai;
        g_tfj[i * CZ + c] = aj;
    }
}

// ---------------- kernel 2: MSA GEMM ----------------
// out[row][c] = sum_k msa[row][k]*w[k][c] + comb[row%768][c]
// 32 rows per CTA, 256 threads. thread = 8 rows x 4 channels, f32x2 FMAs.
// smem: w padded to [50][256] (k=49 zero row) + rows [32][50] (k=49 zero).
#define MSA_SMEM_BYTES (50*256*4 + 32*50*4)   // 57600

__global__ void __launch_bounds__(256) msa_kernel(const float* __restrict__ msa,
                                                  const float* __restrict__ w,
                                                  float* __restrict__ out) {
    extern __shared__ float sm[];
    float* w_sm  = sm;            // 50*256
    float* rows  = sm + 12800;    // 32*50

    int tid = threadIdx.x;

    // weights (+ zero pad row k=49): 12800 floats
    for (int idx = tid; idx < 12800; idx += 256)
        w_sm[idx] = (idx < 12544) ? w[idx] : 0.0f;

    long row0 = (long)blockIdx.x * 32;
    const float* src = msa + row0 * MSADIM;   // 1568 contiguous floats
    for (int idx = tid; idx < 32 * MSADIM; idx += 256) {
        int r = idx / MSADIM;
        int k = idx - r * MSADIM;
        rows[r * 50 + k] = src[idx];
    }
    if (tid < 32) rows[tid * 50 + 49] = 0.0f;
    __syncthreads();

    int cq   = tid & 31;
    int half = (tid >> 5) & 1;
    int set  = tid >> 6;               // 0..3 -> 8-row group
    int c0   = half * 128 + cq * 4;    // 4 channels, conflict-free LDS.128
    int rbase = set * 8;

    ull acc[8][2];
#pragma unroll
    for (int r = 0; r < 8; r++) { acc[r][0] = 0ull; acc[r][1] = 0ull; }

#pragma unroll
    for (int p = 0; p < 25; p++) {
        int k0 = 2 * p;
        ulonglong2 w0 = *(const ulonglong2*)(w_sm + k0 * 256 + c0);        // ch c0..c0+3 @ k0
        ulonglong2 w1 = *(const ulonglong2*)(w_sm + (k0 + 1) * 256 + c0);  // ch c0..c0+3 @ k0+1
#pragma unroll
        for (int r = 0; r < 8; r++) {
            float2 a = *(const float2*)(rows + (rbase + r) * 50 + k0);     // broadcast
            ull a0 = pack2(a.x, a.x);
            ull a1 = pack2(a.y, a.y);
            acc[r][0] = fma2(a0, w0.x, acc[r][0]);
            acc[r][1] = fma2(a0, w0.y, acc[r][1]);
            acc[r][0] = fma2(a1, w1.x, acc[r][0]);
            acc[r][1] = fma2(a1, w1.y, acc[r][1]);
        }
    }

    int n0 = (int)(row0 % NRES);  // row0 multiple of 32; 32 | 768 -> no wrap inside block
#pragma unroll
    for (int r = 0; r < 8; r++) {
        long row = row0 + rbase + r;
        float4 cb = *(const float4*)(g_comb + (n0 + rbase + r) * CM + c0);
        float2 v0 = unpack2(acc[r][0]);
        float2 v1 = unpack2(acc[r][1]);
        float4 o = make_float4(v0.x + cb.x, v0.y + cb.y, v1.x + cb.z, v1.y + cb.w);
        *(float4*)(out + row * (long)CM + c0) = o;
    }
}

// ---------------- kernel 3: pair embedding ----------------
// pair[i][j][c] = w_rel[pos]+ent*w_rel[66]+w_rel[67+chain]+b_rel+tfi[i]+tfj[j]
// grid (768, 4): block = residue i, j-chunk of 192. 256 thr = 8 j-lanes x 32 c-lanes.
__global__ void __launch_bounds__(256) pair_kernel(const int* __restrict__ res,
                                                   const int* __restrict__ sym,
                                                   const int* __restrict__ asym,
                                                   const int* __restrict__ ent,
                                                   const float* __restrict__ w_rel,
                                                   const float* __restrict__ b_rel,
                                                   float* __restrict__ pair_out) {
    __shared__ int s_res[NRES];
    __shared__ int s_sym[NRES];
    __shared__ int s_asym[NRES];
    __shared__ float s_base[CZ];

    int tid = threadIdx.x;
    int i = blockIdx.x;

    for (int t = tid; t < NRES; t += 256) {
        s_res[t]  = res[t];
        s_sym[t]  = sym[t];
        s_asym[t] = asym[t];
    }
    if (tid < CZ) s_base[tid] = b_rel[tid] + g_tfi[i * CZ + tid];
    __syncthreads();

    int cq = tid & 31;
    int jl = tid >> 5;   // 0..7

    int res_i  = s_res[i];
    int sym_i  = s_sym[i];
    int asym_i = s_asym[i];
    int ent_i  = ent[i];

    float4 base4 = ((const float4*)s_base)[cq];
    const float4* W4 = (const float4*)w_rel;
    float4 w66 = W4[66 * 32 + cq];

    int jstart = blockIdx.y * 192;
#pragma unroll 4
    for (int it = 0; it < 24; it++) {
        int j = jstart + it * 8 + jl;
        int rj = s_res[j], sj = s_sym[j], aj = s_asym[j];

        int off = res_i - rj + 32;
        off = min(max(off, 0), 64);
        int pos = (asym_i == aj) ? off : 65;

        int ed = ent_i - sj;
        float entf = (float)ed;

        int cc = sym_i - sj + 2;
        cc = min(max(cc, 0), 4);
        int chain = (ed != 0) ? cc : 5;

        float4 wp = W4[pos * 32 + cq];
        float4 wc = W4[(67 + chain) * 32 + cq];
        float4 tj = ((const float4*)(g_tfj + j * CZ))[cq];

        float4 o;
        o.x = base4.x + wp.x + entf * w66.x + wc.x + tj.x;
        o.y = base4.y + wp.y + entf * w66.y + wc.y + tj.y;
        o.z = base4.z + wp.z + entf * w66.z + wc.z + tj.z;
        o.w = base4.w + wp.w + entf * w66.w + wc.w + tj.w;

        ((float4*)(pair_out + ((size_t)i * NRES + j) * CZ))[cq] = o;
    }
}

// ---------------- launch ----------------
extern "C" void kernel_launch(void* const* d_in, const int* in_sizes, int n_in,
                              void* d_out, int out_size) {
    const float* tf     = (const float*)d_in[0];
    const float* msa    = (const float*)d_in[1];
    const int*   res    = (const int*)d_in[2];
    const int*   sym    = (const int*)d_in[3];
    const int*   asym   = (const int*)d_in[4];
    const int*   ent    = (const int*)d_in[5];
    const float* w_zi   = (const float*)d_in[6];
    const float* b_zi   = (const float*)d_in[7];
    const float* w_zj   = (const float*)d_in[8];
    const float* b_zj   = (const float*)d_in[9];
    const float* w_m    = (const float*)d_in[10];
    const float* b_m    = (const float*)d_in[11];
    const float* w_msa  = (const float*)d_in[12];
    const float* b_msa  = (const float*)d_in[13];
    const float* w_rel  = (const float*)d_in[14];
    const float* b_rel  = (const float*)d_in[15];

    float* msa_out  = (float*)d_out;
    float* pair_out = (float*)d_out + MSA_OUT_ELEMS;

    cudaFuncSetAttribute(msa_kernel, cudaFuncAttributeMaxDynamicSharedMemorySize,
                         MSA_SMEM_BYTES);

    pre_kernel<<<NRES, 256>>>(tf, w_zi, b_zi, w_zj, b_zj, w_m, b_m, b_msa);
    msa_kernel<<<ROWS_TOTAL / 32, 256, MSA_SMEM_BYTES>>>(msa, w_msa, msa_out);
    pair_kernel<<<dim3(NRES, 4), 256>>>(res, sym, asym, ent, w_rel, b_rel, pair_out);
}